// round 2
// baseline (speedup 1.0000x reference)
#include <cuda_runtime.h>
#include <math.h>

#define T_TOK 4096
#define DM 1024
#define DF 4096
#define NE 8
#define NP 8192   // T_TOK * TOP_K

// ---------------- scratch (device globals; no allocations allowed) ----------
__device__ int   g_counts[NE];
__device__ int   g_off[NE + 1];
__device__ int   g_cursor[NE];
__device__ int   g_tok_e[NP];      // [t*2+k] -> expert id
__device__ float g_tok_w[NP];      // [t*2+k] -> combine weight
__device__ int   g_slot_tok[NP];   // sorted slot -> token
__device__ int   g_tok_slot[NP];   // [t*2+k] -> sorted slot
__device__ float g_h[(size_t)NP * DF];   // 134 MB hidden activations
__device__ float g_y[(size_t)NP * DM];   // 32 MB per-pair outputs

// ---------------- init: zero the routing counters every call -----------------
__global__ void init_kernel() {
    if (threadIdx.x < NE) g_counts[threadIdx.x] = 0;
}

// ---------------- gating: one warp per token --------------------------------
__global__ void gate_kernel(const float* __restrict__ x,
                            const float* __restrict__ Wg,
                            const float* __restrict__ bg) {
    int warp = threadIdx.x >> 5, lane = threadIdx.x & 31;
    int t = blockIdx.x * 4 + warp;
    const float* xr = x + (size_t)t * DM;

    float acc[NE];
#pragma unroll
    for (int e = 0; e < NE; e++) acc[e] = 0.f;

    for (int d = lane; d < DM; d += 32) {
        float xv = xr[d];
        const float* wr = Wg + d * NE;
#pragma unroll
        for (int e = 0; e < NE; e++) acc[e] = fmaf(xv, wr[e], acc[e]);
    }
#pragma unroll
    for (int e = 0; e < NE; e++)
#pragma unroll
        for (int o = 16; o > 0; o >>= 1)
            acc[e] += __shfl_xor_sync(0xffffffffu, acc[e], o);

    if (lane == 0) {
        float v[NE];
#pragma unroll
        for (int e = 0; e < NE; e++) v[e] = acc[e] + bg[e];
        // top-2, jax.lax.top_k tie-break: lower index wins (strict >)
        int i0 = 0;
        for (int e = 1; e < NE; e++) if (v[e] > v[i0]) i0 = e;
        int i1 = (i0 == 0) ? 1 : 0;
        for (int e = 0; e < NE; e++) { if (e == i0) continue; if (v[e] > v[i1]) i1 = e; }
        // softmax over the two top logits (v[i0] >= v[i1])
        float e1 = expf(v[i1] - v[i0]);
        float s  = 1.f + e1;
        g_tok_e[2 * t]     = i0;  g_tok_w[2 * t]     = 1.f / s;
        g_tok_e[2 * t + 1] = i1;  g_tok_w[2 * t + 1] = e1 / s;
        atomicAdd(&g_counts[i0], 1);
        atomicAdd(&g_counts[i1], 1);
    }
}

// ---------------- prefix over 8 experts --------------------------------------
__global__ void prefix_kernel() {
    int acc = 0;
    for (int e = 0; e < NE; e++) {
        g_off[e] = acc;
        g_cursor[e] = acc;
        acc += g_counts[e];
    }
    g_off[NE] = acc;
}

// ---------------- scatter pairs into expert-sorted slots ---------------------
__global__ void scatter_kernel() {
    int p = blockIdx.x * blockDim.x + threadIdx.x;
    if (p >= NP) return;
    int e = g_tok_e[p];
    int slot = atomicAdd(&g_cursor[e], 1);
    g_slot_tok[slot] = p >> 1;
    g_tok_slot[p] = slot;
}

// ---------------- GEMM1: h = relu(x_gather @ W1_e + b1) ----------------------
// 128x128 tile, BK=8, 256 threads, 8x8 per thread (2x2 quads of 4x4)
__global__ void __launch_bounds__(256)
gemm1_kernel(const float* __restrict__ x,
             const float* __restrict__ W1,
             const float* __restrict__ b1) {
    int e   = blockIdx.z;
    int off = g_off[e], cnt = g_off[e + 1] - off;
    int m0  = blockIdx.y * 128;
    if (m0 >= cnt) return;
    int n0  = blockIdx.x * 128;
    const float* W1e = W1 + (size_t)e * DM * DF;

    __shared__ float As[8][128];
    __shared__ float Bs[8][128];

    int tid  = threadIdx.x;
    int arow = tid >> 1, ac4 = (tid & 1) * 4;
    int am   = m0 + arow;
    const float* xrow =
        x + ((am < cnt) ? (size_t)g_slot_tok[off + am] * DM : (size_t)0);
    int bk = tid >> 5, bn = (tid & 31) * 4;
    int tx = tid & 15, ty = tid >> 4;

    float acc[8][8];
#pragma unroll
    for (int i = 0; i < 8; i++)
#pragma unroll
        for (int j = 0; j < 8; j++) acc[i][j] = 0.f;

    for (int k0 = 0; k0 < DM; k0 += 8) {
        float4 av = *(const float4*)(xrow + k0 + ac4);
        float4 bv = *(const float4*)(W1e + (size_t)(k0 + bk) * DF + n0 + bn);
        __syncthreads();
        As[ac4 + 0][arow] = av.x; As[ac4 + 1][arow] = av.y;
        As[ac4 + 2][arow] = av.z; As[ac4 + 3][arow] = av.w;
        *(float4*)&Bs[bk][bn] = bv;
        __syncthreads();
#pragma unroll
        for (int kk = 0; kk < 8; kk++) {
            float4 a0 = *(const float4*)&As[kk][ty * 4];
            float4 a1 = *(const float4*)&As[kk][64 + ty * 4];
            float4 bb0 = *(const float4*)&Bs[kk][tx * 4];
            float4 bb1 = *(const float4*)&Bs[kk][64 + tx * 4];
            float a[8] = {a0.x, a0.y, a0.z, a0.w, a1.x, a1.y, a1.z, a1.w};
            float b[8] = {bb0.x, bb0.y, bb0.z, bb0.w, bb1.x, bb1.y, bb1.z, bb1.w};
#pragma unroll
            for (int i = 0; i < 8; i++)
#pragma unroll
                for (int j = 0; j < 8; j++)
                    acc[i][j] = fmaf(a[i], b[j], acc[i][j]);
        }
    }

#pragma unroll
    for (int i = 0; i < 8; i++) {
        int mi = (i < 4) ? (ty * 4 + i) : (64 + ty * 4 + (i - 4));
        int m = m0 + mi;
        if (m >= cnt) continue;
        size_t slot = (size_t)(off + m);
#pragma unroll
        for (int h = 0; h < 2; h++) {
            int cb = n0 + h * 64 + tx * 4;
            const float* b1p = b1 + (size_t)e * DF + cb;
            float4 r;
            r.x = fmaxf(acc[i][h * 4 + 0] + b1p[0], 0.f);
            r.y = fmaxf(acc[i][h * 4 + 1] + b1p[1], 0.f);
            r.z = fmaxf(acc[i][h * 4 + 2] + b1p[2], 0.f);
            r.w = fmaxf(acc[i][h * 4 + 3] + b1p[3], 0.f);
            *(float4*)(g_h + slot * DF + cb) = r;
        }
    }
}

// ---------------- GEMM2: y = h @ W2_e + b2 -----------------------------------
__global__ void __launch_bounds__(256)
gemm2_kernel(const float* __restrict__ W2,
             const float* __restrict__ b2) {
    int e   = blockIdx.z;
    int off = g_off[e], cnt = g_off[e + 1] - off;
    int m0  = blockIdx.y * 128;
    if (m0 >= cnt) return;
    int n0  = blockIdx.x * 128;
    const float* W2e = W2 + (size_t)e * DF * DM;

    __shared__ float As[8][128];
    __shared__ float Bs[8][128];

    int tid  = threadIdx.x;
    int arow = tid >> 1, ac4 = (tid & 1) * 4;
    int am   = m0 + arow;
    const float* hrow =
        g_h + ((am < cnt) ? (size_t)(off + am) * DF : (size_t)0);
    int bk = tid >> 5, bn = (tid & 31) * 4;
    int tx = tid & 15, ty = tid >> 4;

    float acc[8][8];
#pragma unroll
    for (int i = 0; i < 8; i++)
#pragma unroll
        for (int j = 0; j < 8; j++) acc[i][j] = 0.f;

    for (int k0 = 0; k0 < DF; k0 += 8) {
        float4 av = *(const float4*)(hrow + k0 + ac4);
        float4 bv = *(const float4*)(W2e + (size_t)(k0 + bk) * DM + n0 + bn);
        __syncthreads();
        As[ac4 + 0][arow] = av.x; As[ac4 + 1][arow] = av.y;
        As[ac4 + 2][arow] = av.z; As[ac4 + 3][arow] = av.w;
        *(float4*)&Bs[bk][bn] = bv;
        __syncthreads();
#pragma unroll
        for (int kk = 0; kk < 8; kk++) {
            float4 a0 = *(const float4*)&As[kk][ty * 4];
            float4 a1 = *(const float4*)&As[kk][64 + ty * 4];
            float4 bb0 = *(const float4*)&Bs[kk][tx * 4];
            float4 bb1 = *(const float4*)&Bs[kk][64 + tx * 4];
            float a[8] = {a0.x, a0.y, a0.z, a0.w, a1.x, a1.y, a1.z, a1.w};
            float b[8] = {bb0.x, bb0.y, bb0.z, bb0.w, bb1.x, bb1.y, bb1.z, bb1.w};
#pragma unroll
            for (int i = 0; i < 8; i++)
#pragma unroll
                for (int j = 0; j < 8; j++)
                    acc[i][j] = fmaf(a[i], b[j], acc[i][j]);
        }
    }

#pragma unroll
    for (int i = 0; i < 8; i++) {
        int mi = (i < 4) ? (ty * 4 + i) : (64 + ty * 4 + (i - 4));
        int m = m0 + mi;
        if (m >= cnt) continue;
        size_t slot = (size_t)(off + m);
#pragma unroll
        for (int h = 0; h < 2; h++) {
            int cb = n0 + h * 64 + tx * 4;
            const float* b2p = b2 + (size_t)e * DM + cb;
            float4 r;
            r.x = acc[i][h * 4 + 0] + b2p[0];
            r.y = acc[i][h * 4 + 1] + b2p[1];
            r.z = acc[i][h * 4 + 2] + b2p[2];
            r.w = acc[i][h * 4 + 3] + b2p[3];
            *(float4*)(g_y + slot * DM + cb) = r;
        }
    }
}

// ---------------- combine: out[t] = w0*y[s0] + w1*y[s1] ----------------------
__global__ void combine_kernel(float* __restrict__ out) {
    int idx = blockIdx.x * blockDim.x + threadIdx.x;
    int t = idx >> 10, d = idx & 1023;
    int s0 = g_tok_slot[2 * t], s1 = g_tok_slot[2 * t + 1];
    out[idx] = g_tok_w[2 * t]     * g_y[(size_t)s0 * DM + d] +
               g_tok_w[2 * t + 1] * g_y[(size_t)s1 * DM + d];
}

// -----------------------------------------------------------------------------
extern "C" void kernel_launch(void* const* d_in, const int* in_sizes, int n_in,
                              void* d_out, int out_size) {
    const float* x  = (const float*)d_in[0];
    const float* Wg = (const float*)d_in[1];
    const float* bg = (const float*)d_in[2];
    const float* W1 = (const float*)d_in[3];
    const float* b1 = (const float*)d_in[4];
    const float* W2 = (const float*)d_in[5];
    const float* b2 = (const float*)d_in[6];
    float* out = (float*)d_out;

    init_kernel<<<1, 32>>>();
    gate_kernel<<<T_TOK / 4, 128>>>(x, Wg, bg);
    prefix_kernel<<<1, 1>>>();
    scatter_kernel<<<NP / 256, 256>>>();
    gemm1_kernel<<<dim3(DF / 128, NP / 128, NE), 256>>>(x, W1, b1);
    gemm2_kernel<<<dim3(DM / 128, NP / 128, NE), 256>>>(W2, b2);
    combine_kernel<<<(T_TOK * DM) / 256, 256>>>(out);
}

// round 3
// speedup vs baseline: 1.9008x; 1.9008x over previous
#include <cuda_runtime.h>
#include <math.h>
#include <stdint.h>

#define T_TOK 4096
#define DM 1024
#define DF 4096
#define NE 8
#define NP 8192   // T_TOK * TOP_K

#define BM 128
#define BN 128
#define BKK 32
#define ASTR 36    // A smem row stride (floats): conflict-free frag loads
#define BSTR 132   // B smem row stride (floats)

// ---------------- scratch (device globals; no allocations allowed) ----------
__device__ int   g_counts[NE];
__device__ int   g_off[NE + 1];
__device__ int   g_cursor[NE];
__device__ int   g_tok_e[NP];
__device__ float g_tok_w[NP];
__device__ int   g_slot_tok[NP];
__device__ int   g_tok_slot[NP];
__device__ float g_h[(size_t)NP * DF];   // 134 MB hidden activations
__device__ float g_y[(size_t)NP * DM];   // 32 MB per-pair outputs

// ---------------- helpers ----------------------------------------------------
__device__ __forceinline__ uint32_t f2tf(float f) {
    uint32_t r;
    asm("cvt.rna.tf32.f32 %0, %1;" : "=r"(r) : "f"(f));
    return r;
}

__device__ __forceinline__ void mma_tf32(float* c, const uint32_t* a, const uint32_t* b) {
    asm("mma.sync.aligned.m16n8k8.row.col.f32.tf32.tf32.f32 "
        "{%0,%1,%2,%3},{%4,%5,%6,%7},{%8,%9},{%0,%1,%2,%3};"
        : "+f"(c[0]), "+f"(c[1]), "+f"(c[2]), "+f"(c[3])
        : "r"(a[0]), "r"(a[1]), "r"(a[2]), "r"(a[3]), "r"(b[0]), "r"(b[1]));
}

// ---------------- init -------------------------------------------------------
__global__ void init_kernel() {
    if (threadIdx.x < NE) g_counts[threadIdx.x] = 0;
}

// ---------------- gating: one warp per token --------------------------------
__global__ void gate_kernel(const float* __restrict__ x,
                            const float* __restrict__ Wg,
                            const float* __restrict__ bg) {
    int warp = threadIdx.x >> 5, lane = threadIdx.x & 31;
    int t = blockIdx.x * 4 + warp;
    const float* xr = x + (size_t)t * DM;

    float acc[NE];
#pragma unroll
    for (int e = 0; e < NE; e++) acc[e] = 0.f;

    for (int d = lane; d < DM; d += 32) {
        float xv = xr[d];
        const float* wr = Wg + d * NE;
#pragma unroll
        for (int e = 0; e < NE; e++) acc[e] = fmaf(xv, wr[e], acc[e]);
    }
#pragma unroll
    for (int e = 0; e < NE; e++)
#pragma unroll
        for (int o = 16; o > 0; o >>= 1)
            acc[e] += __shfl_xor_sync(0xffffffffu, acc[e], o);

    if (lane == 0) {
        float v[NE];
#pragma unroll
        for (int e = 0; e < NE; e++) v[e] = acc[e] + bg[e];
        int i0 = 0;
        for (int e = 1; e < NE; e++) if (v[e] > v[i0]) i0 = e;
        int i1 = (i0 == 0) ? 1 : 0;
        for (int e = 0; e < NE; e++) { if (e == i0) continue; if (v[e] > v[i1]) i1 = e; }
        float e1 = expf(v[i1] - v[i0]);
        float s  = 1.f + e1;
        g_tok_e[2 * t]     = i0;  g_tok_w[2 * t]     = 1.f / s;
        g_tok_e[2 * t + 1] = i1;  g_tok_w[2 * t + 1] = e1 / s;
        atomicAdd(&g_counts[i0], 1);
        atomicAdd(&g_counts[i1], 1);
    }
}

// ---------------- prefix -----------------------------------------------------
__global__ void prefix_kernel() {
    int acc = 0;
    for (int e = 0; e < NE; e++) {
        g_off[e] = acc;
        g_cursor[e] = acc;
        acc += g_counts[e];
    }
    g_off[NE] = acc;
}

// ---------------- scatter ----------------------------------------------------
__global__ void scatter_kernel() {
    int p = blockIdx.x * blockDim.x + threadIdx.x;
    if (p >= NP) return;
    int e = g_tok_e[p];
    int slot = atomicAdd(&g_cursor[e], 1);
    g_slot_tok[slot] = p >> 1;
    g_tok_slot[p] = slot;
}

// ---------------- GEMM1 (tf32 tensor): h = relu(x_gather @ W1_e + b1) --------
__global__ void __launch_bounds__(256, 2)
gemm1_tc(const float* __restrict__ x,
         const float* __restrict__ W1,
         const float* __restrict__ b1) {
    int e   = blockIdx.z;
    int off = g_off[e], cnt = g_off[e + 1] - off;
    int m0  = blockIdx.y * BM;
    if (m0 >= cnt) return;
    int n0  = blockIdx.x * BN;
    const float* Bsrc = W1 + (size_t)e * DM * DF;
    const float* b1e  = b1 + (size_t)e * DF;

    __shared__ float As[BM][ASTR];
    __shared__ float Bs[BKK][BSTR];

    int tid  = threadIdx.x;
    int lane = tid & 31, wid = tid >> 5;
    int warpM = wid >> 2, warpN = wid & 3;   // 2 x 4
    int gid = lane >> 2, tig = lane & 3;

    // A loader: row per 2 threads, 16 floats each
    int arow = tid >> 1;
    int acb  = (tid & 1) * 16;
    int am   = m0 + arow;
    const float* xrow =
        x + (size_t)g_slot_tok[off + ((am < cnt) ? am : 0)] * DM;
    // B loader: 32 rows x 128 cols, 16 floats/thread
    int brow = tid >> 3;
    int bcb  = (tid & 7) * 16;

    float acc[4][4][4];
#pragma unroll
    for (int mi = 0; mi < 4; mi++)
#pragma unroll
        for (int ni = 0; ni < 4; ni++)
#pragma unroll
            for (int q = 0; q < 4; q++) acc[mi][ni][q] = 0.f;

    for (int k0 = 0; k0 < DM; k0 += BKK) {
        float4 av[4], bv[4];
        const float* bp = Bsrc + (size_t)(k0 + brow) * DF + n0 + bcb;
#pragma unroll
        for (int i = 0; i < 4; i++) av[i] = *(const float4*)(xrow + k0 + acb + 4 * i);
#pragma unroll
        for (int i = 0; i < 4; i++) bv[i] = *(const float4*)(bp + 4 * i);
        __syncthreads();
#pragma unroll
        for (int i = 0; i < 4; i++) *(float4*)&As[arow][acb + 4 * i] = av[i];
#pragma unroll
        for (int i = 0; i < 4; i++) *(float4*)&Bs[brow][bcb + 4 * i] = bv[i];
        __syncthreads();

#pragma unroll
        for (int ks = 0; ks < 4; ks++) {
            int kk = ks * 8;
            uint32_t af[4][4], bf[4][2];
#pragma unroll
            for (int mi = 0; mi < 4; mi++) {
                int r = warpM * 64 + mi * 16 + gid;
                af[mi][0] = f2tf(As[r][kk + tig]);
                af[mi][1] = f2tf(As[r + 8][kk + tig]);
                af[mi][2] = f2tf(As[r][kk + tig + 4]);
                af[mi][3] = f2tf(As[r + 8][kk + tig + 4]);
            }
#pragma unroll
            for (int ni = 0; ni < 4; ni++) {
                int c = warpN * 32 + ni * 8 + gid;
                bf[ni][0] = f2tf(Bs[kk + tig][c]);
                bf[ni][1] = f2tf(Bs[kk + tig + 4][c]);
            }
#pragma unroll
            for (int mi = 0; mi < 4; mi++)
#pragma unroll
                for (int ni = 0; ni < 4; ni++)
                    mma_tf32(acc[mi][ni], af[mi], bf[ni]);
        }
    }

    // epilogue: relu(acc + b1), store to g_h
#pragma unroll
    for (int mi = 0; mi < 4; mi++) {
#pragma unroll
        for (int half = 0; half < 2; half++) {
            int m = m0 + warpM * 64 + mi * 16 + gid + half * 8;
            if (m >= cnt + m0) {}  // (m relative below)
            int mrel = warpM * 64 + mi * 16 + gid + half * 8 + m0;
            if (mrel >= cnt) continue;
            size_t slot = (size_t)(off + mrel);
#pragma unroll
            for (int ni = 0; ni < 4; ni++) {
                int col = n0 + warpN * 32 + ni * 8 + tig * 2;
                float2 v;
                v.x = fmaxf(acc[mi][ni][half * 2 + 0] + b1e[col], 0.f);
                v.y = fmaxf(acc[mi][ni][half * 2 + 1] + b1e[col + 1], 0.f);
                *(float2*)(g_h + slot * DF + col) = v;
            }
        }
    }
}

// ---------------- GEMM2 (tf32 tensor): y = h @ W2_e + b2 ---------------------
__global__ void __launch_bounds__(256, 2)
gemm2_tc(const float* __restrict__ W2,
         const float* __restrict__ b2) {
    int e   = blockIdx.z;
    int off = g_off[e], cnt = g_off[e + 1] - off;
    int m0  = blockIdx.y * BM;
    if (m0 >= cnt) return;
    int n0  = blockIdx.x * BN;
    const float* Bsrc = W2 + (size_t)e * DF * DM;
    const float* b2e  = b2 + (size_t)e * DM;

    __shared__ float As[BM][ASTR];
    __shared__ float Bs[BKK][BSTR];

    int tid  = threadIdx.x;
    int lane = tid & 31, wid = tid >> 5;
    int warpM = wid >> 2, warpN = wid & 3;
    int gid = lane >> 2, tig = lane & 3;

    int arow = tid >> 1;
    int acb  = (tid & 1) * 16;
    int am   = m0 + arow;
    const float* hrow =
        g_h + (size_t)(off + ((am < cnt) ? am : 0)) * DF;
    int brow = tid >> 3;
    int bcb  = (tid & 7) * 16;

    float acc[4][4][4];
#pragma unroll
    for (int mi = 0; mi < 4; mi++)
#pragma unroll
        for (int ni = 0; ni < 4; ni++)
#pragma unroll
            for (int q = 0; q < 4; q++) acc[mi][ni][q] = 0.f;

    for (int k0 = 0; k0 < DF; k0 += BKK) {
        float4 av[4], bv[4];
        const float* bp = Bsrc + (size_t)(k0 + brow) * DM + n0 + bcb;
#pragma unroll
        for (int i = 0; i < 4; i++) av[i] = *(const float4*)(hrow + k0 + acb + 4 * i);
#pragma unroll
        for (int i = 0; i < 4; i++) bv[i] = *(const float4*)(bp + 4 * i);
        __syncthreads();
#pragma unroll
        for (int i = 0; i < 4; i++) *(float4*)&As[arow][acb + 4 * i] = av[i];
#pragma unroll
        for (int i = 0; i < 4; i++) *(float4*)&Bs[brow][bcb + 4 * i] = bv[i];
        __syncthreads();

#pragma unroll
        for (int ks = 0; ks < 4; ks++) {
            int kk = ks * 8;
            uint32_t af[4][4], bf[4][2];
#pragma unroll
            for (int mi = 0; mi < 4; mi++) {
                int r = warpM * 64 + mi * 16 + gid;
                af[mi][0] = f2tf(As[r][kk + tig]);
                af[mi][1] = f2tf(As[r + 8][kk + tig]);
                af[mi][2] = f2tf(As[r][kk + tig + 4]);
                af[mi][3] = f2tf(As[r + 8][kk + tig + 4]);
            }
#pragma unroll
            for (int ni = 0; ni < 4; ni++) {
                int c = warpN * 32 + ni * 8 + gid;
                bf[ni][0] = f2tf(Bs[kk + tig][c]);
                bf[ni][1] = f2tf(Bs[kk + tig + 4][c]);
            }
#pragma unroll
            for (int mi = 0; mi < 4; mi++)
#pragma unroll
                for (int ni = 0; ni < 4; ni++)
                    mma_tf32(acc[mi][ni], af[mi], bf[ni]);
        }
    }

#pragma unroll
    for (int mi = 0; mi < 4; mi++) {
#pragma unroll
        for (int half = 0; half < 2; half++) {
            int mrel = m0 + warpM * 64 + mi * 16 + gid + half * 8;
            if (mrel >= cnt) continue;
            size_t slot = (size_t)(off + mrel);
#pragma unroll
            for (int ni = 0; ni < 4; ni++) {
                int col = n0 + warpN * 32 + ni * 8 + tig * 2;
                float2 v;
                v.x = acc[mi][ni][half * 2 + 0] + b2e[col];
                v.y = acc[mi][ni][half * 2 + 1] + b2e[col + 1];
                *(float2*)(g_y + slot * DM + col) = v;
            }
        }
    }
}

// ---------------- combine ----------------------------------------------------
__global__ void combine_kernel(float* __restrict__ out) {
    int idx = blockIdx.x * blockDim.x + threadIdx.x;
    int t = idx >> 10, d = idx & 1023;
    int s0 = g_tok_slot[2 * t], s1 = g_tok_slot[2 * t + 1];
    out[idx] = g_tok_w[2 * t]     * g_y[(size_t)s0 * DM + d] +
               g_tok_w[2 * t + 1] * g_y[(size_t)s1 * DM + d];
}

// -----------------------------------------------------------------------------
extern "C" void kernel_launch(void* const* d_in, const int* in_sizes, int n_in,
                              void* d_out, int out_size) {
    const float* x  = (const float*)d_in[0];
    const float* Wg = (const float*)d_in[1];
    const float* bg = (const float*)d_in[2];
    const float* W1 = (const float*)d_in[3];
    const float* b1 = (const float*)d_in[4];
    const float* W2 = (const float*)d_in[5];
    const float* b2 = (const float*)d_in[6];
    float* out = (float*)d_out;

    init_kernel<<<1, 32>>>();
    gate_kernel<<<T_TOK / 4, 128>>>(x, Wg, bg);
    prefix_kernel<<<1, 1>>>();
    scatter_kernel<<<NP / 256, 256>>>();
    // per-expert segment max is T_TOK rows (a token picks an expert at most once)
    gemm1_tc<<<dim3(DF / BN, T_TOK / BM, NE), 256>>>(x, W1, b1);
    gemm2_tc<<<dim3(DM / BN, T_TOK / BM, NE), 256>>>(W2, b2);
    combine_kernel<<<(T_TOK * DM) / 256, 256>>>(out);
}

// round 5
// speedup vs baseline: 3.1731x; 1.6693x over previous
#include <cuda_runtime.h>
#include <cuda_fp16.h>
#include <math.h>
#include <stdint.h>

#define T_TOK 4096
#define DM 1024
#define DF 4096
#define NE 8
#define NP 8192   // T_TOK * TOP_K

#define BM 128
#define BN 256
#define BK 32
#define NST 3
#define STAGE_BYTES 24576      // A: 128*64B = 8KB, B: 32*512B = 16KB
#define B_OFF 8192
#define SMEM_DYN (NST * STAGE_BYTES)

// ---------------- scratch (device globals; no runtime allocations) ----------
__device__ int    g_counts[NE];
__device__ int    g_off[NE + 1];
__device__ int    g_cursor[NE];
__device__ int    g_tok_e[NP];
__device__ float  g_tok_w[NP];
__device__ int    g_slot_tok[NP];
__device__ int    g_tok_slot[NP];
__device__ __half g_w1h[(size_t)NE * DM * DF];   // 67 MB
__device__ __half g_w2h[(size_t)NE * DF * DM];   // 67 MB
__device__ __half g_xh[(size_t)T_TOK * DM];      // 8 MB
__device__ __half g_h[(size_t)NP * DF];          // 67 MB hidden acts (fp16)
__device__ float  g_y[(size_t)NP * DM];          // 32 MB per-pair outputs

// ---------------- PTX helpers ------------------------------------------------
__device__ __forceinline__ uint32_t smem_u32(const void* p) {
    uint32_t a;
    asm("{ .reg .u64 t; cvta.to.shared.u64 t, %1; cvt.u32.u64 %0, t; }"
        : "=r"(a) : "l"(p));
    return a;
}

__device__ __forceinline__ void cp16(uint32_t s, const void* g) {
    asm volatile("cp.async.cg.shared.global [%0], [%1], 16;"
                 :: "r"(s), "l"(g) : "memory");
}
#define CP_COMMIT() asm volatile("cp.async.commit_group;" ::: "memory")
#define CP_WAIT1()  asm volatile("cp.async.wait_group 1;" ::: "memory")

__device__ __forceinline__ void ldsm_x4(uint32_t* r, uint32_t addr) {
    asm volatile("ldmatrix.sync.aligned.m8n8.x4.shared.b16 {%0,%1,%2,%3}, [%4];"
                 : "=r"(r[0]), "=r"(r[1]), "=r"(r[2]), "=r"(r[3]) : "r"(addr));
}
__device__ __forceinline__ void ldsm_x4_t(uint32_t* r, uint32_t addr) {
    asm volatile("ldmatrix.sync.aligned.m8n8.x4.trans.shared.b16 {%0,%1,%2,%3}, [%4];"
                 : "=r"(r[0]), "=r"(r[1]), "=r"(r[2]), "=r"(r[3]) : "r"(addr));
}
__device__ __forceinline__ void mma_16816(float* c, const uint32_t* a,
                                          const uint32_t* b) {
    asm volatile(
        "mma.sync.aligned.m16n8k16.row.col.f32.f16.f16.f32 "
        "{%0,%1,%2,%3},{%4,%5,%6,%7},{%8,%9},{%0,%1,%2,%3};"
        : "+f"(c[0]), "+f"(c[1]), "+f"(c[2]), "+f"(c[3])
        : "r"(a[0]), "r"(a[1]), "r"(a[2]), "r"(a[3]), "r"(b[0]), "r"(b[1]));
}

// ---------------- init -------------------------------------------------------
__global__ void init_kernel() {
    if (threadIdx.x < NE) g_counts[threadIdx.x] = 0;
}

// ---------------- fp32 -> fp16 convert (vectorized) --------------------------
__global__ void cvt_kernel(const float* __restrict__ src,
                           __half* __restrict__ dst, int n4) {
    int i = blockIdx.x * blockDim.x + threadIdx.x;
    if (i < n4) {
        float4 v = ((const float4*)src)[i];
        __half2 h0 = __floats2half2_rn(v.x, v.y);
        __half2 h1 = __floats2half2_rn(v.z, v.w);
        ((__half2*)dst)[2 * i]     = h0;
        ((__half2*)dst)[2 * i + 1] = h1;
    }
}

// ---------------- gating: one warp per token ---------------------------------
__global__ void gate_kernel(const float* __restrict__ x,
                            const float* __restrict__ Wg,
                            const float* __restrict__ bg) {
    int warp = threadIdx.x >> 5, lane = threadIdx.x & 31;
    int t = blockIdx.x * 4 + warp;
    const float* xr = x + (size_t)t * DM;

    float acc[NE];
#pragma unroll
    for (int e = 0; e < NE; e++) acc[e] = 0.f;

    for (int d = lane; d < DM; d += 32) {
        float xv = xr[d];
        const float* wr = Wg + d * NE;
#pragma unroll
        for (int e = 0; e < NE; e++) acc[e] = fmaf(xv, wr[e], acc[e]);
    }
#pragma unroll
    for (int e = 0; e < NE; e++)
#pragma unroll
        for (int o = 16; o > 0; o >>= 1)
            acc[e] += __shfl_xor_sync(0xffffffffu, acc[e], o);

    if (lane == 0) {
        float v[NE];
#pragma unroll
        for (int e = 0; e < NE; e++) v[e] = acc[e] + bg[e];
        int i0 = 0;
        for (int e = 1; e < NE; e++) if (v[e] > v[i0]) i0 = e;
        int i1 = (i0 == 0) ? 1 : 0;
        for (int e = 0; e < NE; e++) { if (e == i0) continue; if (v[e] > v[i1]) i1 = e; }
        float e1 = expf(v[i1] - v[i0]);
        float s  = 1.f + e1;
        g_tok_e[2 * t]     = i0;  g_tok_w[2 * t]     = 1.f / s;
        g_tok_e[2 * t + 1] = i1;  g_tok_w[2 * t + 1] = e1 / s;
        atomicAdd(&g_counts[i0], 1);
        atomicAdd(&g_counts[i1], 1);
    }
}

// ---------------- prefix -----------------------------------------------------
__global__ void prefix_kernel() {
    int acc = 0;
    for (int e = 0; e < NE; e++) {
        g_off[e] = acc;
        g_cursor[e] = acc;
        acc += g_counts[e];
    }
    g_off[NE] = acc;
}

// ---------------- scatter ----------------------------------------------------
__global__ void scatter_kernel() {
    int p = blockIdx.x * blockDim.x + threadIdx.x;
    if (p >= NP) return;
    int e = g_tok_e[p];
    int slot = atomicAdd(&g_cursor[e], 1);
    g_slot_tok[slot] = p >> 1;
    g_tok_slot[p] = slot;
}

// ---------------- fp16 tensor GEMM (mma.sync + cp.async + ldmatrix) ----------
// C[BM, BN] tile of  A[seg rows, KDIM] x W_e[KDIM, OUTD].
// A smem: [128 rows][32 halfs] (64B/row), phys chunk = c ^ ((row>>1)&3)
// B smem: [32 k-rows][256 halfs] (512B/row), phys chunk = c ^ (k&7)
template <int KDIM, int OUTD, bool G1>
__global__ void __launch_bounds__(512, 1)
gemm_h(const float* __restrict__ bias) {
    extern __shared__ char smraw[];
    uint32_t sb = smem_u32(smraw);
    int tid = threadIdx.x, lane = tid & 31, wid = tid >> 5;
    int e = blockIdx.z;
    int off = g_off[e], cnt = g_off[e + 1] - off;
    int m0 = blockIdx.y * BM;
    if (m0 >= cnt) return;
    int n0 = blockIdx.x * BN;
    const __half* W = (G1 ? g_w1h : g_w2h) + (size_t)e * KDIM * OUTD;
    const float* be = bias + (size_t)e * OUTD;

    // ---- A loader: thread t -> row t&127, 16B chunk t>>7 (of 4)
    int arow = tid & 127;
    int ac   = tid >> 7;
    int amr  = m0 + arow; if (amr >= cnt) amr = cnt - 1;
    const __half* aptr;
    if (G1) aptr = g_xh + (size_t)g_slot_tok[off + amr] * KDIM + ac * 8;
    else    aptr = g_h  + (size_t)(off + amr) * KDIM + ac * 8;
    uint32_t a_dst = sb + arow * 64 + ((uint32_t)(ac ^ ((arow >> 1) & 3))) * 16;

    // ---- B loader: thread t -> k-row t>>4, 16B chunks (t&15) and (t&15)+16
    int bk = tid >> 4;
    int bc = tid & 15;
    const __half* bptr = W + (size_t)bk * OUTD + n0;
    uint32_t b_dst0 = sb + B_OFF + bk * 512 + ((uint32_t)(bc        ^ (bk & 7))) * 16;
    uint32_t b_dst1 = sb + B_OFF + bk * 512 + ((uint32_t)((bc + 16) ^ (bk & 7))) * 16;
    int bo0 = bc * 8, bo1 = (bc + 16) * 8;

    // ---- fragment addressing
    int warpM = wid & 1, warpN = wid >> 1;        // 2 x 8 warps, 64 x 32 tiles
    int rA   = warpM * 64 + (lane & 15);
    uint32_t swzA = (rA >> 1) & 3;
    uint32_t aFb  = sb + rA * 64;                  // + stage + mi*1024 + chunk*16
    int hi   = lane >> 4;
    uint32_t bFb  = sb + B_OFF + (lane & 15) * 512; // + stage + ks*16*512 + chunk*16
    uint32_t swzB = lane & 7;

    float acc[4][4][4];
#pragma unroll
    for (int mi = 0; mi < 4; mi++)
#pragma unroll
        for (int ni = 0; ni < 4; ni++)
#pragma unroll
            for (int q = 0; q < 4; q++) acc[mi][ni][q] = 0.f;

    const int NC = KDIM / BK;

    // ---- prologue: stages 0, 1
#pragma unroll
    for (int s = 0; s < NST - 1; s++) {
        uint32_t so = s * STAGE_BYTES;
        cp16(a_dst + so, aptr + (size_t)s * BK);
        const __half* bp = bptr + (size_t)s * BK * OUTD;
        cp16(b_dst0 + so, bp + bo0);
        cp16(b_dst1 + so, bp + bo1);
        CP_COMMIT();
    }

    for (int c = 0; c < NC; c++) {
        CP_WAIT1();
        __syncthreads();

        int nc = c + NST - 1;
        if (nc < NC) {
            uint32_t so = (nc % NST) * STAGE_BYTES;
            cp16(a_dst + so, aptr + (size_t)nc * BK);
            const __half* bp = bptr + (size_t)nc * BK * OUTD;
            cp16(b_dst0 + so, bp + bo0);
            cp16(b_dst1 + so, bp + bo1);
        }
        CP_COMMIT();

        uint32_t so = (c % NST) * STAGE_BYTES;
#pragma unroll
        for (int ks = 0; ks < 2; ks++) {
            uint32_t a[4][4], b[2][4];
#pragma unroll
            for (int mi = 0; mi < 4; mi++)
                ldsm_x4(a[mi], aFb + so + mi * 1024 +
                        ((uint32_t)((ks * 2 + hi) ^ swzA)) * 16);
#pragma unroll
            for (int p = 0; p < 2; p++)
                ldsm_x4_t(b[p], bFb + so + ks * 16 * 512 +
                          ((uint32_t)((warpN * 4 + p * 2 + hi) ^ swzB)) * 16);
#pragma unroll
            for (int mi = 0; mi < 4; mi++)
#pragma unroll
                for (int ni = 0; ni < 4; ni++)
                    mma_16816(acc[mi][ni], a[mi], &b[ni >> 1][(ni & 1) * 2]);
        }
    }

    // ---- epilogue
    int gid = lane >> 2, tig = lane & 3;
#pragma unroll
    for (int mi = 0; mi < 4; mi++) {
#pragma unroll
        for (int h2 = 0; h2 < 2; h2++) {
            int mrel = m0 + warpM * 64 + mi * 16 + gid + h2 * 8;
            if (mrel >= cnt) continue;
            size_t rowbase = (size_t)(off + mrel) * OUTD;
#pragma unroll
            for (int ni = 0; ni < 4; ni++) {
                int col = n0 + warpN * 32 + ni * 8 + 2 * tig;
                float v0 = acc[mi][ni][h2 * 2 + 0] + be[col];
                float v1 = acc[mi][ni][h2 * 2 + 1] + be[col + 1];
                if (G1) {
                    v0 = fmaxf(v0, 0.f);
                    v1 = fmaxf(v1, 0.f);
                    *(__half2*)(g_h + rowbase + col) = __floats2half2_rn(v0, v1);
                } else {
                    float2 v; v.x = v0; v.y = v1;
                    *(float2*)(g_y + rowbase + col) = v;
                }
            }
        }
    }
}

// ---------------- combine ----------------------------------------------------
__global__ void combine_kernel(float* __restrict__ out) {
    int idx = blockIdx.x * blockDim.x + threadIdx.x;
    int t = idx >> 10, d = idx & 1023;
    int s0 = g_tok_slot[2 * t], s1 = g_tok_slot[2 * t + 1];
    out[idx] = g_tok_w[2 * t]     * g_y[(size_t)s0 * DM + d] +
               g_tok_w[2 * t + 1] * g_y[(size_t)s1 * DM + d];
}

// -----------------------------------------------------------------------------
extern "C" void kernel_launch(void* const* d_in, const int* in_sizes, int n_in,
                              void* d_out, int out_size) {
    const float* x  = (const float*)d_in[0];
    const float* Wg = (const float*)d_in[1];
    const float* bg = (const float*)d_in[2];
    const float* W1 = (const float*)d_in[3];
    const float* b1 = (const float*)d_in[4];
    const float* W2 = (const float*)d_in[5];
    const float* b2 = (const float*)d_in[6];
    float* out = (float*)d_out;

    cudaFuncSetAttribute(gemm_h<DM, DF, true>,
                         cudaFuncAttributeMaxDynamicSharedMemorySize, SMEM_DYN);
    cudaFuncSetAttribute(gemm_h<DF, DM, false>,
                         cudaFuncAttributeMaxDynamicSharedMemorySize, SMEM_DYN);

    __half* w1h; cudaGetSymbolAddress((void**)&w1h, g_w1h);
    __half* w2h; cudaGetSymbolAddress((void**)&w2h, g_w2h);
    __half* xh;  cudaGetSymbolAddress((void**)&xh,  g_xh);

    init_kernel<<<1, 32>>>();
    cvt_kernel<<<(NE * DM * DF / 4) / 256, 256>>>(W1, w1h, NE * DM * DF / 4);
    cvt_kernel<<<(NE * DF * DM / 4) / 256, 256>>>(W2, w2h, NE * DF * DM / 4);
    cvt_kernel<<<(T_TOK * DM / 4) / 256, 256>>>(x, xh, T_TOK * DM / 4);
    gate_kernel<<<T_TOK / 4, 128>>>(x, Wg, bg);
    prefix_kernel<<<1, 1>>>();
    scatter_kernel<<<NP / 256, 256>>>();
    gemm_h<DM, DF, true><<<dim3(DF / BN, T_TOK / BM, NE), 512, SMEM_DYN>>>(b1);
    gemm_h<DF, DM, false><<<dim3(DM / BN, T_TOK / BM, NE), 512, SMEM_DYN>>>(b2);
    combine_kernel<<<(T_TOK * DM) / 256, 256>>>(out);
}

// round 6
// speedup vs baseline: 4.4297x; 1.3960x over previous
#include <cuda_runtime.h>
#include <cuda_fp16.h>
#include <math.h>
#include <stdint.h>

#define T_TOK 4096
#define DM 1024
#define DF 4096
#define NE 8
#define NP 8192   // T_TOK * TOP_K

#define BM 128
#define BN 128
#define BK 32
#define NST 4
#define STAGE_BYTES 16384      // A: 128*64B = 8KB, B: 32*256B = 8KB
#define B_OFF 8192
#define SMEM_DYN (NST * STAGE_BYTES)

#define N4_W1 (NE * DM * DF / 4)
#define N4_W2 (NE * DF * DM / 4)
#define N4_X  (T_TOK * DM / 4)
#define N4_ALL (N4_W1 + N4_W2 + N4_X)

// ---------------- scratch (device globals; no runtime allocations) ----------
__device__ int    g_off[NE + 1];
__device__ int    g_tok_e[NP];
__device__ float  g_tok_w[NP];
__device__ int    g_slot_tok[NP];
__device__ int    g_tok_slot[NP];
__device__ __half g_w1h[(size_t)NE * DM * DF];   // 67 MB
__device__ __half g_w2h[(size_t)NE * DF * DM];   // 67 MB
__device__ __half g_xh[(size_t)T_TOK * DM];      // 8 MB
__device__ __half g_h[(size_t)NP * DF];          // 67 MB hidden acts (fp16)
__device__ float  g_y[(size_t)NP * DM];          // 32 MB per-pair outputs

// ---------------- PTX helpers ------------------------------------------------
__device__ __forceinline__ uint32_t smem_u32(const void* p) {
    uint32_t a;
    asm("{ .reg .u64 t; cvta.to.shared.u64 t, %1; cvt.u32.u64 %0, t; }"
        : "=r"(a) : "l"(p));
    return a;
}

__device__ __forceinline__ void cp16(uint32_t s, const void* g) {
    asm volatile("cp.async.cg.shared.global [%0], [%1], 16;"
                 :: "r"(s), "l"(g) : "memory");
}
#define CP_COMMIT() asm volatile("cp.async.commit_group;" ::: "memory")
#define CP_WAIT2()  asm volatile("cp.async.wait_group 2;" ::: "memory")

__device__ __forceinline__ void ldsm_x4(uint32_t* r, uint32_t addr) {
    asm volatile("ldmatrix.sync.aligned.m8n8.x4.shared.b16 {%0,%1,%2,%3}, [%4];"
                 : "=r"(r[0]), "=r"(r[1]), "=r"(r[2]), "=r"(r[3]) : "r"(addr));
}
__device__ __forceinline__ void ldsm_x4_t(uint32_t* r, uint32_t addr) {
    asm volatile("ldmatrix.sync.aligned.m8n8.x4.trans.shared.b16 {%0,%1,%2,%3}, [%4];"
                 : "=r"(r[0]), "=r"(r[1]), "=r"(r[2]), "=r"(r[3]) : "r"(addr));
}
__device__ __forceinline__ void mma_16816(float* c, const uint32_t* a,
                                          const uint32_t* b) {
    asm volatile(
        "mma.sync.aligned.m16n8k16.row.col.f32.f16.f16.f32 "
        "{%0,%1,%2,%3},{%4,%5,%6,%7},{%8,%9},{%0,%1,%2,%3};"
        : "+f"(c[0]), "+f"(c[1]), "+f"(c[2]), "+f"(c[3])
        : "r"(a[0]), "r"(a[1]), "r"(a[2]), "r"(a[3]), "r"(b[0]), "r"(b[1]));
}

// ---------------- gating: one warp per token (no atomics) --------------------
__global__ void gate_kernel(const float* __restrict__ x,
                            const float* __restrict__ Wg,
                            const float* __restrict__ bg) {
    int warp = threadIdx.x >> 5, lane = threadIdx.x & 31;
    int t = blockIdx.x * 4 + warp;
    const float* xr = x + (size_t)t * DM;

    float acc[NE];
#pragma unroll
    for (int e = 0; e < NE; e++) acc[e] = 0.f;

    for (int d = lane; d < DM; d += 32) {
        float xv = xr[d];
        const float* wr = Wg + d * NE;
#pragma unroll
        for (int e = 0; e < NE; e++) acc[e] = fmaf(xv, wr[e], acc[e]);
    }
#pragma unroll
    for (int e = 0; e < NE; e++)
#pragma unroll
        for (int o = 16; o > 0; o >>= 1)
            acc[e] += __shfl_xor_sync(0xffffffffu, acc[e], o);

    if (lane == 0) {
        float v[NE];
#pragma unroll
        for (int e = 0; e < NE; e++) v[e] = acc[e] + bg[e];
        int i0 = 0;
        for (int e = 1; e < NE; e++) if (v[e] > v[i0]) i0 = e;
        int i1 = (i0 == 0) ? 1 : 0;
        for (int e = 0; e < NE; e++) { if (e == i0) continue; if (v[e] > v[i1]) i1 = e; }
        float e1 = expf(v[i1] - v[i0]);
        float s  = 1.f + e1;
        g_tok_e[2 * t]     = i0;  g_tok_w[2 * t]     = 1.f / s;
        g_tok_e[2 * t + 1] = i1;  g_tok_w[2 * t + 1] = e1 / s;
    }
}

// ---------------- route: single block, count + prefix + scatter --------------
__global__ void route_kernel() {
    __shared__ int cnt[NE], cur[NE];
    int tid = threadIdx.x;
    if (tid < NE) cnt[tid] = 0;
    __syncthreads();
    for (int p = tid; p < NP; p += blockDim.x)
        atomicAdd(&cnt[g_tok_e[p]], 1);
    __syncthreads();
    if (tid == 0) {
        int acc = 0;
        for (int e = 0; e < NE; e++) {
            g_off[e] = acc;
            cur[e] = acc;
            acc += cnt[e];
        }
        g_off[NE] = acc;
    }
    __syncthreads();
    for (int p = tid; p < NP; p += blockDim.x) {
        int slot = atomicAdd(&cur[g_tok_e[p]], 1);
        g_slot_tok[slot] = p >> 1;
        g_tok_slot[p] = slot;
    }
}

// ---------------- fused fp32 -> fp16 convert (W1 | W2 | x) -------------------
__global__ void cvt_all_kernel(const float* __restrict__ W1,
                               const float* __restrict__ W2,
                               const float* __restrict__ x) {
    int i = blockIdx.x * blockDim.x + threadIdx.x;
    if (i >= N4_ALL) return;
    const float* src;
    __half* dst;
    int j;
    if (i < N4_W1)                 { src = W1; dst = g_w1h; j = i; }
    else if (i < N4_W1 + N4_W2)    { src = W2; dst = g_w2h; j = i - N4_W1; }
    else                           { src = x;  dst = g_xh;  j = i - N4_W1 - N4_W2; }
    float4 v = ((const float4*)src)[j];
    ((__half2*)dst)[2 * j]     = __floats2half2_rn(v.x, v.y);
    ((__half2*)dst)[2 * j + 1] = __floats2half2_rn(v.z, v.w);
}

// ---------------- fp16 tensor GEMM (mma.sync + cp.async + ldmatrix) ----------
// C[BM=128, BN=128] tile. 256 threads, 8 warps (2 M x 4 N), warp tile 64x32.
// A smem: [128 rows][32 halfs] (64B row, 4 chunks), phys chunk = c ^ ((row>>1)&3)
// B smem: [32 k-rows][128 halfs] (256B row, 16 chunks), phys chunk = c ^ (k&7)
template <int KDIM, int OUTD, bool G1>
__global__ void __launch_bounds__(256, 2)
gemm_h(const float* __restrict__ bias) {
    extern __shared__ char smraw[];
    uint32_t sb = smem_u32(smraw);
    int tid = threadIdx.x, lane = tid & 31, wid = tid >> 5;
    int e = blockIdx.z;
    int off = g_off[e], cnt = g_off[e + 1] - off;
    int m0 = blockIdx.y * BM;
    if (m0 >= cnt) return;
    int n0 = blockIdx.x * BN;
    const __half* W = (G1 ? g_w1h : g_w2h) + (size_t)e * KDIM * OUTD;
    const float* be = bias + (size_t)e * OUTD;

    // ---- A loader: thread t -> row t&127, chunks (t>>7) and (t>>7)+2
    int arow = tid & 127;
    int ac   = tid >> 7;              // 0..1
    int amr  = m0 + arow; if (amr >= cnt) amr = cnt - 1;
    const __half* aptr;
    if (G1) aptr = g_xh + (size_t)g_slot_tok[off + amr] * KDIM;
    else    aptr = g_h  + (size_t)(off + amr) * KDIM;
    uint32_t a_dst0 = sb + arow * 64 + ((uint32_t)(ac       ^ ((arow >> 1) & 3))) * 16;
    uint32_t a_dst1 = sb + arow * 64 + ((uint32_t)((ac + 2) ^ ((arow >> 1) & 3))) * 16;
    int ao0 = ac * 8, ao1 = (ac + 2) * 8;

    // ---- B loader: thread t -> k-row t>>3, chunks (t&7) and (t&7)+8
    int bk = tid >> 3;                // 0..31
    int bc = tid & 7;
    const __half* bptr = W + (size_t)bk * OUTD + n0;
    uint32_t b_dst0 = sb + B_OFF + bk * 256 + ((uint32_t)(bc       ^ (bk & 7))) * 16;
    uint32_t b_dst1 = sb + B_OFF + bk * 256 + ((uint32_t)((bc + 8) ^ (bk & 7))) * 16;
    int bo0 = bc * 8, bo1 = (bc + 8) * 8;

    // ---- fragment addressing: warpM = wid&1 (64 rows), warpN = wid>>1 (32 cols)
    int warpM = wid & 1, warpN = wid >> 1;
    int rA   = warpM * 64 + (lane & 15);
    uint32_t swzA = (rA >> 1) & 3;
    uint32_t aFb  = sb + rA * 64;                   // + stage + mi*1024 + chunk*16
    int hi   = lane >> 4;
    uint32_t bFb  = sb + B_OFF + (lane & 15) * 256; // + stage + ks*16*256 + chunk*16
    uint32_t swzB = lane & 7;

    float acc[4][4][4];
#pragma unroll
    for (int mi = 0; mi < 4; mi++)
#pragma unroll
        for (int ni = 0; ni < 4; ni++)
#pragma unroll
            for (int q = 0; q < 4; q++) acc[mi][ni][q] = 0.f;

    const int NC = KDIM / BK;

    // ---- prologue: stages 0..NST-2
#pragma unroll
    for (int s = 0; s < NST - 1; s++) {
        uint32_t so = s * STAGE_BYTES;
        cp16(a_dst0 + so, aptr + (size_t)s * BK + ao0);
        cp16(a_dst1 + so, aptr + (size_t)s * BK + ao1);
        const __half* bp = bptr + (size_t)s * BK * OUTD;
        cp16(b_dst0 + so, bp + bo0);
        cp16(b_dst1 + so, bp + bo1);
        CP_COMMIT();
    }

    for (int c = 0; c < NC; c++) {
        CP_WAIT2();
        __syncthreads();

        int nc = c + NST - 1;
        if (nc < NC) {
            uint32_t so = (nc % NST) * STAGE_BYTES;
            cp16(a_dst0 + so, aptr + (size_t)nc * BK + ao0);
            cp16(a_dst1 + so, aptr + (size_t)nc * BK + ao1);
            const __half* bp = bptr + (size_t)nc * BK * OUTD;
            cp16(b_dst0 + so, bp + bo0);
            cp16(b_dst1 + so, bp + bo1);
        }
        CP_COMMIT();

        uint32_t so = (c % NST) * STAGE_BYTES;
#pragma unroll
        for (int ks = 0; ks < 2; ks++) {
            uint32_t a[4][4], b[2][4];
#pragma unroll
            for (int mi = 0; mi < 4; mi++)
                ldsm_x4(a[mi], aFb + so + mi * 1024 +
                        ((uint32_t)((ks * 2 + hi) ^ swzA)) * 16);
#pragma unroll
            for (int p = 0; p < 2; p++)
                ldsm_x4_t(b[p], bFb + so + ks * 16 * 256 +
                          ((uint32_t)((warpN * 4 + p * 2 + hi) ^ swzB)) * 16);
#pragma unroll
            for (int mi = 0; mi < 4; mi++)
#pragma unroll
                for (int ni = 0; ni < 4; ni++)
                    mma_16816(acc[mi][ni], a[mi], &b[ni >> 1][(ni & 1) * 2]);
        }
    }

    // ---- epilogue
    int gid = lane >> 2, tig = lane & 3;
#pragma unroll
    for (int mi = 0; mi < 4; mi++) {
#pragma unroll
        for (int h2 = 0; h2 < 2; h2++) {
            int mrel = m0 + warpM * 64 + mi * 16 + gid + h2 * 8;
            if (mrel >= cnt) continue;
            size_t rowbase = (size_t)(off + mrel) * OUTD;
#pragma unroll
            for (int ni = 0; ni < 4; ni++) {
                int col = n0 + warpN * 32 + ni * 8 + 2 * tig;
                float v0 = acc[mi][ni][h2 * 2 + 0] + be[col];
                float v1 = acc[mi][ni][h2 * 2 + 1] + be[col + 1];
                if (G1) {
                    v0 = fmaxf(v0, 0.f);
                    v1 = fmaxf(v1, 0.f);
                    *(__half2*)(g_h + rowbase + col) = __floats2half2_rn(v0, v1);
                } else {
                    float2 v; v.x = v0; v.y = v1;
                    *(float2*)(g_y + rowbase + col) = v;
                }
            }
        }
    }
}

// ---------------- combine ----------------------------------------------------
__global__ void combine_kernel(float* __restrict__ out) {
    int idx = blockIdx.x * blockDim.x + threadIdx.x;
    int t = idx >> 10, d = idx & 1023;
    int s0 = g_tok_slot[2 * t], s1 = g_tok_slot[2 * t + 1];
    out[idx] = g_tok_w[2 * t]     * g_y[(size_t)s0 * DM + d] +
               g_tok_w[2 * t + 1] * g_y[(size_t)s1 * DM + d];
}

// -----------------------------------------------------------------------------
extern "C" void kernel_launch(void* const* d_in, const int* in_sizes, int n_in,
                              void* d_out, int out_size) {
    const float* x  = (const float*)d_in[0];
    const float* Wg = (const float*)d_in[1];
    const float* bg = (const float*)d_in[2];
    const float* W1 = (const float*)d_in[3];
    const float* b1 = (const float*)d_in[4];
    const float* W2 = (const float*)d_in[5];
    const float* b2 = (const float*)d_in[6];
    float* out = (float*)d_out;

    cudaFuncSetAttribute(gemm_h<DM, DF, true>,
                         cudaFuncAttributeMaxDynamicSharedMemorySize, SMEM_DYN);
    cudaFuncSetAttribute(gemm_h<DF, DM, false>,
                         cudaFuncAttributeMaxDynamicSharedMemorySize, SMEM_DYN);

    // launch order chosen so the 4th launch (ncu capture point) is gemm1
    gate_kernel<<<T_TOK / 4, 128>>>(x, Wg, bg);
    route_kernel<<<1, 1024>>>();
    cvt_all_kernel<<<(N4_ALL + 255) / 256, 256>>>(W1, W2, x);
    gemm_h<DM, DF, true><<<dim3(DF / BN, T_TOK / BM, NE), 256, SMEM_DYN>>>(b1);
    gemm_h<DF, DM, false><<<dim3(DM / BN, T_TOK / BM, NE), 256, SMEM_DYN>>>(b2);
    combine_kernel<<<(T_TOK * DM) / 256, 256>>>(out);
}

// round 7
// speedup vs baseline: 4.5197x; 1.0203x over previous
#include <cuda_runtime.h>
#include <cuda_fp16.h>
#include <math.h>
#include <stdint.h>

#define T_TOK 4096
#define DM 1024
#define DF 4096
#define NE 8
#define NP 8192   // T_TOK * TOP_K

#define BM 128
#define BN 256
#define BK 64
#define NST 3
#define STAGE_BYTES 49152      // A: 128*128B = 16KB, B: 64*512B = 32KB
#define B_OFF 16384
#define SMEM_DYN (NST * STAGE_BYTES)   // 144 KB

#define N4_W1 (NE * DM * DF / 4)
#define N4_W2 (NE * DF * DM / 4)
#define N4_X  (T_TOK * DM / 4)
#define N4_ALL (N4_W1 + N4_W2 + N4_X)

// ---------------- scratch (device globals; no runtime allocations) ----------
__device__ int    g_off[NE + 1];
__device__ int    g_tok_e[NP];
__device__ float  g_tok_w[NP];
__device__ int    g_slot_tok[NP];
__device__ int    g_tok_slot[NP];
__device__ __half g_w1h[(size_t)NE * DM * DF];   // 67 MB
__device__ __half g_w2h[(size_t)NE * DF * DM];   // 67 MB
__device__ __half g_xh[(size_t)T_TOK * DM];      // 8 MB
__device__ __half g_h[(size_t)NP * DF];          // 67 MB hidden acts (fp16)
__device__ float  g_y[(size_t)NP * DM];          // 32 MB per-pair outputs

// ---------------- PTX helpers ------------------------------------------------
__device__ __forceinline__ uint32_t smem_u32(const void* p) {
    uint32_t a;
    asm("{ .reg .u64 t; cvta.to.shared.u64 t, %1; cvt.u32.u64 %0, t; }"
        : "=r"(a) : "l"(p));
    return a;
}

__device__ __forceinline__ void cp16(uint32_t s, const void* g) {
    asm volatile("cp.async.cg.shared.global [%0], [%1], 16;"
                 :: "r"(s), "l"(g) : "memory");
}
#define CP_COMMIT() asm volatile("cp.async.commit_group;" ::: "memory")
#define CP_WAIT1()  asm volatile("cp.async.wait_group 1;" ::: "memory")

__device__ __forceinline__ void ldsm_x4(uint32_t* r, uint32_t addr) {
    asm volatile("ldmatrix.sync.aligned.m8n8.x4.shared.b16 {%0,%1,%2,%3}, [%4];"
                 : "=r"(r[0]), "=r"(r[1]), "=r"(r[2]), "=r"(r[3]) : "r"(addr));
}
__device__ __forceinline__ void ldsm_x4_t(uint32_t* r, uint32_t addr) {
    asm volatile("ldmatrix.sync.aligned.m8n8.x4.trans.shared.b16 {%0,%1,%2,%3}, [%4];"
                 : "=r"(r[0]), "=r"(r[1]), "=r"(r[2]), "=r"(r[3]) : "r"(addr));
}
__device__ __forceinline__ void mma_16816(float* c, const uint32_t* a,
                                          const uint32_t* b) {
    asm volatile(
        "mma.sync.aligned.m16n8k16.row.col.f32.f16.f16.f32 "
        "{%0,%1,%2,%3},{%4,%5,%6,%7},{%8,%9},{%0,%1,%2,%3};"
        : "+f"(c[0]), "+f"(c[1]), "+f"(c[2]), "+f"(c[3])
        : "r"(a[0]), "r"(a[1]), "r"(a[2]), "r"(a[3]), "r"(b[0]), "r"(b[1]));
}

// ---------------- gating: one warp per token (no atomics) --------------------
__global__ void gate_kernel(const float* __restrict__ x,
                            const float* __restrict__ Wg,
                            const float* __restrict__ bg) {
    int warp = threadIdx.x >> 5, lane = threadIdx.x & 31;
    int t = blockIdx.x * 4 + warp;
    const float* xr = x + (size_t)t * DM;

    float acc[NE];
#pragma unroll
    for (int e = 0; e < NE; e++) acc[e] = 0.f;

    for (int d = lane; d < DM; d += 32) {
        float xv = xr[d];
        const float* wr = Wg + d * NE;
#pragma unroll
        for (int e = 0; e < NE; e++) acc[e] = fmaf(xv, wr[e], acc[e]);
    }
#pragma unroll
    for (int e = 0; e < NE; e++)
#pragma unroll
        for (int o = 16; o > 0; o >>= 1)
            acc[e] += __shfl_xor_sync(0xffffffffu, acc[e], o);

    if (lane == 0) {
        float v[NE];
#pragma unroll
        for (int e = 0; e < NE; e++) v[e] = acc[e] + bg[e];
        int i0 = 0;
        for (int e = 1; e < NE; e++) if (v[e] > v[i0]) i0 = e;
        int i1 = (i0 == 0) ? 1 : 0;
        for (int e = 0; e < NE; e++) { if (e == i0) continue; if (v[e] > v[i1]) i1 = e; }
        float e1 = expf(v[i1] - v[i0]);
        float s  = 1.f + e1;
        g_tok_e[2 * t]     = i0;  g_tok_w[2 * t]     = 1.f / s;
        g_tok_e[2 * t + 1] = i1;  g_tok_w[2 * t + 1] = e1 / s;
    }
}

// ---------------- route: single block, count + prefix + scatter --------------
__global__ void route_kernel() {
    __shared__ int cnt[NE], cur[NE];
    int tid = threadIdx.x;
    if (tid < NE) cnt[tid] = 0;
    __syncthreads();
    for (int p = tid; p < NP; p += blockDim.x)
        atomicAdd(&cnt[g_tok_e[p]], 1);
    __syncthreads();
    if (tid == 0) {
        int acc = 0;
        for (int e = 0; e < NE; e++) {
            g_off[e] = acc;
            cur[e] = acc;
            acc += cnt[e];
        }
        g_off[NE] = acc;
    }
    __syncthreads();
    for (int p = tid; p < NP; p += blockDim.x) {
        int slot = atomicAdd(&cur[g_tok_e[p]], 1);
        g_slot_tok[slot] = p >> 1;
        g_tok_slot[p] = slot;
    }
}

// ---------------- fused fp32 -> fp16 convert (W1 | W2 | x) -------------------
__global__ void cvt_all_kernel(const float* __restrict__ W1,
                               const float* __restrict__ W2,
                               const float* __restrict__ x) {
    int i = blockIdx.x * blockDim.x + threadIdx.x;
    if (i >= N4_ALL) return;
    const float* src;
    __half* dst;
    int j;
    if (i < N4_W1)                 { src = W1; dst = g_w1h; j = i; }
    else if (i < N4_W1 + N4_W2)    { src = W2; dst = g_w2h; j = i - N4_W1; }
    else                           { src = x;  dst = g_xh;  j = i - N4_W1 - N4_W2; }
    float4 v = ((const float4*)src)[j];
    ((__half2*)dst)[2 * j]     = __floats2half2_rn(v.x, v.y);
    ((__half2*)dst)[2 * j + 1] = __floats2half2_rn(v.z, v.w);
}

// ---------------- fp16 tensor GEMM -------------------------------------------
// CTA tile 128x256, BK=64. 256 threads, 8 warps (2 M x 4 N), warp tile 64x64.
// A smem: [128 rows][64 halfs] (128B row, 8 chunks), phys chunk = c ^ (row&7)
// B smem: [64 k-rows][256 halfs] (512B row, 32 chunks), phys chunk = c ^ (k&7)
template <int KDIM, int OUTD, bool G1>
__global__ void __launch_bounds__(256, 1)
gemm_h(const float* __restrict__ bias) {
    extern __shared__ char smraw[];
    uint32_t sb = smem_u32(smraw);
    int tid = threadIdx.x, lane = tid & 31, wid = tid >> 5;
    int e = blockIdx.z;
    int off = g_off[e], cnt = g_off[e + 1] - off;
    int m0 = blockIdx.y * BM;
    if (m0 >= cnt) return;
    int n0 = blockIdx.x * BN;
    const __half* W = (G1 ? g_w1h : g_w2h) + (size_t)e * KDIM * OUTD;
    const float* be = bias + (size_t)e * OUTD;

    // ---- A loader: thread t -> row t&127, chunks (t>>7) + 2i, i=0..3
    int arow = tid & 127;
    int ac   = tid >> 7;              // 0..1
    int amr  = m0 + arow; if (amr >= cnt) amr = cnt - 1;
    const __half* aptr;
    if (G1) aptr = g_xh + (size_t)g_slot_tok[off + amr] * KDIM;
    else    aptr = g_h  + (size_t)(off + amr) * KDIM;
    uint32_t a_dst[4];
    int a_go[4];
#pragma unroll
    for (int i = 0; i < 4; i++) {
        int c = ac + 2 * i;
        a_dst[i] = sb + arow * 128 + ((uint32_t)(c ^ (arow & 7))) * 16;
        a_go[i]  = c * 8;
    }

    // ---- B loader: thread t -> k-row t>>2, chunks (t&3) + 4j, j=0..7
    int bk = tid >> 2;                // 0..63
    int blo = tid & 3;
    const __half* bptr = W + (size_t)bk * OUTD + n0;
    uint32_t b_dst[8];
    int b_go[8];
#pragma unroll
    for (int j = 0; j < 8; j++) {
        int c = blo + 4 * j;
        b_dst[j] = sb + B_OFF + bk * 512 + ((uint32_t)(c ^ (bk & 7))) * 16;
        b_go[j]  = c * 8;
    }

    // ---- fragment addressing: warpM = wid&1 (64 rows), warpN = wid>>1 (64 cols)
    int warpM = wid & 1, warpN = wid >> 1;
    uint32_t aFb = sb + (warpM * 64 + (lane & 15)) * 128;  // + so + mi*2048 + chunk*16
    int hi = lane >> 4;
    uint32_t bFb = sb + B_OFF + (lane & 15) * 512;         // + so + ks*8192 + chunk*16
    uint32_t swz = lane & 7;

    float acc[4][8][4];
#pragma unroll
    for (int mi = 0; mi < 4; mi++)
#pragma unroll
        for (int ni = 0; ni < 8; ni++)
#pragma unroll
            for (int q = 0; q < 4; q++) acc[mi][ni][q] = 0.f;

    const int NC = KDIM / BK;

    // ---- prologue: stages 0, 1
#pragma unroll
    for (int s = 0; s < NST - 1; s++) {
        uint32_t so = s * STAGE_BYTES;
        const __half* ap = aptr + (size_t)s * BK;
        const __half* bp = bptr + (size_t)s * BK * OUTD;
#pragma unroll
        for (int i = 0; i < 4; i++) cp16(a_dst[i] + so, ap + a_go[i]);
#pragma unroll
        for (int j = 0; j < 8; j++) cp16(b_dst[j] + so, bp + b_go[j]);
        CP_COMMIT();
    }

    for (int c = 0; c < NC; c++) {
        CP_WAIT1();
        __syncthreads();

        int nc = c + NST - 1;
        if (nc < NC) {
            uint32_t so = (nc % NST) * STAGE_BYTES;
            const __half* ap = aptr + (size_t)nc * BK;
            const __half* bp = bptr + (size_t)nc * BK * OUTD;
#pragma unroll
            for (int i = 0; i < 4; i++) cp16(a_dst[i] + so, ap + a_go[i]);
#pragma unroll
            for (int j = 0; j < 8; j++) cp16(b_dst[j] + so, bp + b_go[j]);
        }
        CP_COMMIT();

        uint32_t so = (c % NST) * STAGE_BYTES;
#pragma unroll
        for (int ks = 0; ks < 4; ks++) {
            uint32_t a[4][4], b[4][4];
#pragma unroll
            for (int mi = 0; mi < 4; mi++)
                ldsm_x4(a[mi], aFb + so + mi * 2048 +
                        ((uint32_t)((ks * 2 + hi) ^ swz)) * 16);
#pragma unroll
            for (int p = 0; p < 4; p++)
                ldsm_x4_t(b[p], bFb + so + ks * 8192 +
                          ((uint32_t)((warpN * 8 + p * 2 + hi) ^ swz)) * 16);
#pragma unroll
            for (int mi = 0; mi < 4; mi++)
#pragma unroll
                for (int ni = 0; ni < 8; ni++)
                    mma_16816(acc[mi][ni], a[mi], &b[ni >> 1][(ni & 1) * 2]);
        }
    }

    // ---- epilogue
    int gid = lane >> 2, tig = lane & 3;
#pragma unroll
    for (int mi = 0; mi < 4; mi++) {
#pragma unroll
        for (int h2 = 0; h2 < 2; h2++) {
            int mrel = m0 + warpM * 64 + mi * 16 + gid + h2 * 8;
            if (mrel >= cnt) continue;
            size_t rowbase = (size_t)(off + mrel) * OUTD;
#pragma unroll
            for (int ni = 0; ni < 8; ni++) {
                int col = n0 + warpN * 64 + ni * 8 + 2 * tig;
                float v0 = acc[mi][ni][h2 * 2 + 0] + be[col];
                float v1 = acc[mi][ni][h2 * 2 + 1] + be[col + 1];
                if (G1) {
                    v0 = fmaxf(v0, 0.f);
                    v1 = fmaxf(v1, 0.f);
                    *(__half2*)(g_h + rowbase + col) = __floats2half2_rn(v0, v1);
                } else {
                    float2 v; v.x = v0; v.y = v1;
                    *(float2*)(g_y + rowbase + col) = v;
                }
            }
        }
    }
}

// ---------------- combine ----------------------------------------------------
__global__ void combine_kernel(float* __restrict__ out) {
    int idx = blockIdx.x * blockDim.x + threadIdx.x;
    int t = idx >> 10, d = idx & 1023;
    int s0 = g_tok_slot[2 * t], s1 = g_tok_slot[2 * t + 1];
    out[idx] = g_tok_w[2 * t]     * g_y[(size_t)s0 * DM + d] +
               g_tok_w[2 * t + 1] * g_y[(size_t)s1 * DM + d];
}

// -----------------------------------------------------------------------------
extern "C" void kernel_launch(void* const* d_in, const int* in_sizes, int n_in,
                              void* d_out, int out_size) {
    const float* x  = (const float*)d_in[0];
    const float* Wg = (const float*)d_in[1];
    const float* bg = (const float*)d_in[2];
    const float* W1 = (const float*)d_in[3];
    const float* b1 = (const float*)d_in[4];
    const float* W2 = (const float*)d_in[5];
    const float* b2 = (const float*)d_in[6];
    float* out = (float*)d_out;

    cudaFuncSetAttribute(gemm_h<DM, DF, true>,
                         cudaFuncAttributeMaxDynamicSharedMemorySize, SMEM_DYN);
    cudaFuncSetAttribute(gemm_h<DF, DM, false>,
                         cudaFuncAttributeMaxDynamicSharedMemorySize, SMEM_DYN);

    // launch order chosen so the 4th launch (ncu capture point) is gemm1
    gate_kernel<<<T_TOK / 4, 128>>>(x, Wg, bg);
    route_kernel<<<1, 1024>>>();
    cvt_all_kernel<<<(N4_ALL + 255) / 256, 256>>>(W1, W2, x);
    gemm_h<DM, DF, true><<<dim3(DF / BN, T_TOK / BM, NE), 256, SMEM_DYN>>>(b1);
    gemm_h<DF, DM, false><<<dim3(DM / BN, T_TOK / BM, NE), 256, SMEM_DYN>>>(b2);
    combine_kernel<<<(T_TOK * DM) / 256, 256>>>(out);
}